// round 13
// baseline (speedup 1.0000x reference)
#include <cuda_runtime.h>
#include <math.h>

#define ANGR 9
#define NVIEW 81
#define HH 96
#define WW 96
#define HW 9216
#define CF 7
#define BB 2

static const float NINIT_F = 2.0f * 81.0f * 9216.0f;  // 1492992
static const float NAGG_F  = 2.0f * 9216.0f;          // 18432

// ---------------- device scratch (no allocations allowed) ----------------
__device__ float g_fA[BB * CF * NVIEW * HW];   // 41.8 MB
__device__ float g_fB[BB * CF * NVIEW * HW];   // 41.8 MB
__device__ float g_y0[BB * 180 * HW];          // 13.3 MB
__device__ float g_y1[BB * 180 * HW];          // 13.3 MB
__device__ float g_acc[18 * 2 * 192];          // per-layer [sum, sumsq] per channel

// ---------------- zero the stat accumulators ----------------
__global__ void k_zero() {
    int t = blockIdx.x * blockDim.x + threadIdx.x;
    if (t < 18 * 2 * 192) g_acc[t] = 0.f;
}

// ---------------- inline BN finalize from batch stats ----------------
__device__ __forceinline__ void bn_from_acc(int L, float invN,
                                            const float* __restrict__ g,
                                            const float* __restrict__ b,
                                            int c, float& sc, float& sh) {
    float s = g_acc[(L * 2 + 0) * 192 + c];
    float q = g_acc[(L * 2 + 1) * 192 + c];
    float m = s * invN;
    float var = fmaxf(q * invN - m * m, 0.f);
    sc = g[c] * rsqrtf(var + 1e-5f);
    sh = b[c] - m * sc;
}

// ---------------- conv0: 1 -> 7, per-view 3x3, input from x (SAI) ---------
__global__ __launch_bounds__(192)
void k_conv0(const float* __restrict__ in, float* __restrict__ out,
             const float* __restrict__ w) {
    __shared__ float sW[63];
    __shared__ float sPart[6][14];
    int t = threadIdx.y * 96 + threadIdx.x;
    if (t < 63) sW[t] = w[t];
    __syncthreads();

    int b = blockIdx.z, view = blockIdx.y;
    int j = threadIdx.x;
    int i0 = blockIdx.x * 8 + threadIdx.y * 4;

    const float* ibase = in + (size_t)b * 864 * 864
                       + (size_t)(view / ANGR) * 96 * 864 + (size_t)(view % ANGR) * 96;

    float colv[3][6];
#pragma unroll
    for (int rr = 0; rr < 6; ++rr) {
        int i = i0 - 1 + rr;
#pragma unroll
        for (int cc = 0; cc < 3; ++cc) {
            int jj = j - 1 + cc;
            float v = 0.f;
            if (i >= 0 && i < HH && jj >= 0 && jj < WW) v = ibase[i * 864 + jj];
            colv[cc][rr] = v;
        }
    }

    float acc[CF][4];
#pragma unroll
    for (int co = 0; co < CF; ++co)
#pragma unroll
        for (int p = 0; p < 4; ++p) acc[co][p] = 0.f;

#pragma unroll
    for (int ky = 0; ky < 3; ++ky)
#pragma unroll
        for (int kx = 0; kx < 3; ++kx) {
            float wr[CF];
#pragma unroll
            for (int co = 0; co < CF; ++co) wr[co] = sW[co * 9 + ky * 3 + kx];
#pragma unroll
            for (int p = 0; p < 4; ++p) {
                float v = colv[kx][p + ky];
#pragma unroll
                for (int co = 0; co < CF; ++co)
                    acc[co][p] = fmaf(v, wr[co], acc[co][p]);
            }
        }

    float ls[CF], ls2[CF];
#pragma unroll
    for (int co = 0; co < CF; ++co) { ls[co] = 0.f; ls2[co] = 0.f; }
#pragma unroll
    for (int co = 0; co < CF; ++co) {
        float* op = out + ((size_t)(b * CF + co) * NVIEW + view) * HW + j;
#pragma unroll
        for (int p = 0; p < 4; ++p) {
            float y = acc[co][p];
            op[(i0 + p) * WW] = y;
            ls[co] += y; ls2[co] += y * y;
        }
    }
    int lane = t & 31, warp = t >> 5;
#pragma unroll
    for (int co = 0; co < CF; ++co) {
        float s = ls[co], q = ls2[co];
#pragma unroll
        for (int off = 16; off > 0; off >>= 1) {
            s += __shfl_xor_sync(0xffffffffu, s, off);
            q += __shfl_xor_sync(0xffffffffu, q, off);
        }
        if (lane == 0) { sPart[warp][co] = s; sPart[warp][7 + co] = q; }
    }
    __syncthreads();
    if (t < 14) {
        float tot = 0.f;
#pragma unroll
        for (int wp = 0; wp < 6; ++wp) tot += sPart[wp][t];
        atomicAdd(&g_acc[(0 * 2 + (t / 7)) * 192 + (t % 7)], tot);
    }
}

// ---------------- conv7: 7 -> 7 per-view 3x3, smem tile, 4 rows/thread -----
// R8 shape (block (96,2), grid (12,81,2), 10-row tile) but weights repacked
// [cin][tap][co pad8] so each tap loads 7 cout-weights via two LDS.128.
__global__ __launch_bounds__(192)
void k_conv7(const float* __restrict__ in, float* __restrict__ out,
             const float* __restrict__ w,
             const float* __restrict__ gIn, const float* __restrict__ bIn,
             int Lin, int statL) {
    __shared__ float sIn[7][10][100];                 // 7000 floats
    __shared__ __align__(16) float sW[7 * 9 * 8];     // 504 floats, [cin][tap][co8]
    __shared__ float sSc[7], sSh[7];
    __shared__ float sPart[6][14];

    int t = threadIdx.y * 96 + threadIdx.x;
    if (t < 7) {
        float sc, sh;
        bn_from_acc(Lin, 1.f / NINIT_F, gIn, bIn, t, sc, sh);
        sSc[t] = sc; sSh[t] = sh;
    }
    // repack weights: global layout [co][cin][tap] -> smem [cin][tap][co]
    for (int s = t; s < 504; s += 192) {
        int co = s & 7;
        int tap = (s >> 3) % 9;
        int cin = s / 72;
        sW[s] = (co < 7) ? w[co * 63 + cin * 9 + tap] : 0.f;
    }
    __syncthreads();

    int b = blockIdx.z, view = blockIdx.y;
    int i0 = blockIdx.x * 8;
    const float* ib = in + ((size_t)(b * CF) * NVIEW + view) * HW;

    // fill 7 x 10 x 100 zero-padded tile, BN+ReLU at load
#pragma unroll
    for (int c = 0; c < 7; ++c) {
        float sc = sSc[c], sh = sSh[c];
        const float* ic = ib + (size_t)c * NVIEW * HW;
        for (int s = t; s < 1000; s += 192) {
            int r = s / 100;
            int col = s - r * 100;
            int ii = i0 - 1 + r, jj = col - 1;
            float v = 0.f;
            if (ii >= 0 && ii < HH && jj >= 0 && jj < WW)
                v = fmaxf(fmaf(ic[ii * WW + jj], sc, sh), 0.f);
            sIn[c][r][col] = v;
        }
    }
    __syncthreads();

    int j = threadIdx.x;
    int r0 = threadIdx.y * 4;

    float acc[CF][4];
#pragma unroll
    for (int co = 0; co < CF; ++co)
#pragma unroll
        for (int p = 0; p < 4; ++p) acc[co][p] = 0.f;

#pragma unroll
    for (int cin = 0; cin < CF; ++cin) {
        float colv[3][6];
#pragma unroll
        for (int rr = 0; rr < 6; ++rr)
#pragma unroll
            for (int cc = 0; cc < 3; ++cc)
                colv[cc][rr] = sIn[cin][r0 + rr][j + cc];
#pragma unroll
        for (int ky = 0; ky < 3; ++ky)
#pragma unroll
            for (int kx = 0; kx < 3; ++kx) {
                const float4* wp = reinterpret_cast<const float4*>(
                    &sW[(cin * 9 + ky * 3 + kx) * 8]);
                float4 w0 = wp[0];
                float4 w1 = wp[1];
                float wr[CF] = {w0.x, w0.y, w0.z, w0.w, w1.x, w1.y, w1.z};
#pragma unroll
                for (int p = 0; p < 4; ++p) {
                    float v = colv[kx][p + ky];
#pragma unroll
                    for (int co = 0; co < CF; ++co)
                        acc[co][p] = fmaf(v, wr[co], acc[co][p]);
                }
            }
    }

    int iout = i0 + r0;
    float ls[CF], ls2[CF];
#pragma unroll
    for (int co = 0; co < CF; ++co) { ls[co] = 0.f; ls2[co] = 0.f; }
#pragma unroll
    for (int co = 0; co < CF; ++co) {
        float* op = out + ((size_t)(b * CF + co) * NVIEW + view) * HW + j;
#pragma unroll
        for (int p = 0; p < 4; ++p) {
            float y = acc[co][p];
            op[(iout + p) * WW] = y;
            ls[co] += y; ls2[co] += y * y;
        }
    }

    int lane = t & 31, warp = t >> 5;
#pragma unroll
    for (int co = 0; co < CF; ++co) {
        float s = ls[co], q = ls2[co];
#pragma unroll
        for (int off = 16; off > 0; off >>= 1) {
            s += __shfl_xor_sync(0xffffffffu, s, off);
            q += __shfl_xor_sync(0xffffffffu, q, off);
        }
        if (lane == 0) { sPart[warp][co] = s; sPart[warp][7 + co] = q; }
    }
    __syncthreads();
    if (t < 14) {
        float tot = 0.f;
#pragma unroll
        for (int wp = 0; wp < 6; ++wp) tot += sPart[wp][t];
        atomicAdd(&g_acc[(statL * 2 + (t / 7)) * 192 + (t % 7)], tot);
    }
}

// ---------------- fused disp_shift + BuildCost (plane sweep) ----------------
__global__ __launch_bounds__(256)
void k_buildcost(const float* __restrict__ f, float* __restrict__ cv,
                 const float* __restrict__ bcw,
                 const float* __restrict__ g6, const float* __restrict__ b6) {
    extern __shared__ float sm[];
    float* sW = sm;            // 81*7*16 = 9072 floats
    float* sT = sm + 9072;     // 7*32*32 = 7168 floats
    __shared__ float sSc[CF], sSh[CF];

    int t = threadIdx.x;
    int b = blockIdx.z, g = blockIdx.y;
    int d = g - 4;
    int y0 = (blockIdx.x / 3) * 32, x0 = (blockIdx.x % 3) * 32;

    if (t < CF) {
        float sc, sh;
        bn_from_acc(6, 1.f / NINIT_F, g6, b6, t, sc, sh);
        sSc[t] = sc; sSh[t] = sh;
    }
    for (int s = t; s < 9072; s += 256) {
        int o = s & 15;
        int c = (s >> 4) % 7;
        int uv = s / 112;
        int u = uv / 9, v = uv % 9;
        int uvs = (d > 0) ? ((8 - u) * 9 + (8 - v)) : uv;
        sW[s] = bcw[((size_t)(16 * g + o) * 7 + c) * 81 + uvs];
    }
    __syncthreads();

    int tx = t & 31, ty0 = t >> 5;
    float acc[4][16];
#pragma unroll
    for (int p = 0; p < 4; ++p)
#pragma unroll
        for (int o = 0; o < 16; ++o) acc[p][o] = 0.f;

    const float* fb = f + (size_t)b * CF * NVIEW * HW;

    for (int uv = 0; uv < 81; ++uv) {
        int u = uv / 9, v = uv % 9;
        int sy = y0 - d * (u - 4), sx = x0 - d * (v - 4);
        for (int s = t; s < 7168; s += 256) {
            int c = s >> 10;
            int pp = s & 1023;
            int r = pp >> 5, cc = pp & 31;
            int ii = sy + r, jj = sx + cc;
            float val = 0.f;
            if (ii >= 0 && ii < HH && jj >= 0 && jj < WW)
                val = fmaxf(fmaf(fb[((size_t)c * NVIEW + uv) * HW + ii * WW + jj],
                                 sSc[c], sSh[c]), 0.f);
            sT[s] = val;
        }
        __syncthreads();
        const float* wuv = sW + uv * 112;
#pragma unroll
        for (int c = 0; c < 7; ++c) {
            float wr[16];
#pragma unroll
            for (int o = 0; o < 16; ++o) wr[o] = wuv[c * 16 + o];
#pragma unroll
            for (int p = 0; p < 4; ++p) {
                float v = sT[c * 1024 + (ty0 + 8 * p) * 32 + tx];
#pragma unroll
                for (int o = 0; o < 16; ++o)
                    acc[p][o] = fmaf(v, wr[o], acc[p][o]);
            }
        }
        __syncthreads();
    }

#pragma unroll
    for (int o = 0; o < 16; ++o) {
        float* op = cv + ((size_t)b * 144 + 16 * g + o) * HW;
#pragma unroll
        for (int p = 0; p < 4; ++p)
            op[(y0 + ty0 + 8 * p) * WW + (x0 + tx)] = acc[p][o];
    }
}

// ---------------- depthwise 3x3 (pad 1), optional input BN+ReLU ------------
__global__ __launch_bounds__(256)
void k_dw(const float* __restrict__ in, float* __restrict__ out,
          const float* __restrict__ w, int C, int Lin, float invN,
          const float* __restrict__ gIn, const float* __restrict__ bIn,
          int statL) {
    int c = blockIdx.x, b = blockIdx.y, t = threadIdx.x;
    float wr[9];
#pragma unroll
    for (int k = 0; k < 9; ++k) wr[k] = w[c * 9 + k];
    float sc = 1.f, sh = 0.f;
    bool act = (Lin >= 0);
    if (act) bn_from_acc(Lin, invN, gIn, bIn, c, sc, sh);
    const float* ip = in + ((size_t)b * C + c) * HW;
    float* op = out + ((size_t)b * C + c) * HW;
    float ls = 0.f, ls2 = 0.f;
    for (int p = t; p < HW; p += 256) {
        int i = p / 96, j = p - i * 96;
        float sum = 0.f;
#pragma unroll
        for (int dy = -1; dy <= 1; ++dy)
#pragma unroll
            for (int dx = -1; dx <= 1; ++dx) {
                int ii = i + dy, jj = j + dx;
                if (ii >= 0 && ii < HH && jj >= 0 && jj < WW) {
                    float v = ip[ii * WW + jj];
                    if (act) v = fmaxf(fmaf(v, sc, sh), 0.f);
                    sum = fmaf(v, wr[(dy + 1) * 3 + dx + 1], sum);
                }
            }
        op[p] = sum; ls += sum; ls2 += sum * sum;
    }
    __shared__ float sP[8][2];
    int lane = t & 31, wp = t >> 5;
#pragma unroll
    for (int off = 16; off > 0; off >>= 1) {
        ls  += __shfl_xor_sync(0xffffffffu, ls, off);
        ls2 += __shfl_xor_sync(0xffffffffu, ls2, off);
    }
    if (lane == 0) { sP[wp][0] = ls; sP[wp][1] = ls2; }
    __syncthreads();
    if (t == 0) {
        float a = 0.f, q = 0.f;
#pragma unroll
        for (int k = 0; k < 8; ++k) { a += sP[k][0]; q += sP[k][1]; }
        atomicAdd(&g_acc[(statL * 2 + 0) * 192 + c], a);
        atomicAdd(&g_acc[(statL * 2 + 1) * 192 + c], q);
    }
}

// ---------------- pointwise conv = GEMM [Cout x Cin] x [Cin x 9216] --------
// BM=64 (cout) x BN=64 (pix) x BK=16; 256 threads, 4x4 per thread.
__global__ __launch_bounds__(256)
void k_pw(const float* __restrict__ in, float* __restrict__ out,
          const float* __restrict__ w, int Cin, int Cout, int Lin,
          const float* __restrict__ gIn, const float* __restrict__ bIn,
          int statL) {
    __shared__ __align__(16) float sA[16 * 64];
    __shared__ __align__(16) float sB[16 * 64];
    __shared__ float sSc[192], sSh[192];
    int t = threadIdx.x;
    int n0 = blockIdx.x * 64, m0 = blockIdx.y * 64, b = blockIdx.z;
    for (int c = t; c < Cin; c += 256) {
        float sc, sh;
        bn_from_acc(Lin, 1.f / NAGG_F, gIn, bIn, c, sc, sh);
        sSc[c] = sc; sSh[c] = sh;
    }
    int tm = (t >> 4) << 2, tn = (t & 15) << 2;
    float acc[4][4];
#pragma unroll
    for (int i2 = 0; i2 < 4; ++i2)
#pragma unroll
        for (int j2 = 0; j2 < 4; ++j2) acc[i2][j2] = 0.f;
    int Kt = (Cin + 15) >> 4;
    __syncthreads();
    for (int kt = 0; kt < Kt; ++kt) {
        int k0 = kt << 4;
#pragma unroll
        for (int r = 0; r < 4; ++r) {
            int s = t + r * 256;
            int k = s >> 6, mn = s & 63;
            int ci = k0 + k;
            int co = m0 + mn;
            sA[s] = (ci < Cin && co < Cout) ? w[(size_t)co * Cin + ci] : 0.f;
            float xv = 0.f;
            if (ci < Cin)
                xv = fmaxf(fmaf(in[((size_t)b * Cin + ci) * HW + n0 + mn], sSc[ci], sSh[ci]), 0.f);
            sB[s] = xv;
        }
        __syncthreads();
#pragma unroll
        for (int kk = 0; kk < 16; ++kk) {
            float4 av = *reinterpret_cast<const float4*>(&sA[kk * 64 + tm]);
            float4 bv = *reinterpret_cast<const float4*>(&sB[kk * 64 + tn]);
            float a[4] = {av.x, av.y, av.z, av.w};
            float bb2[4] = {bv.x, bv.y, bv.z, bv.w};
#pragma unroll
            for (int i2 = 0; i2 < 4; ++i2)
#pragma unroll
                for (int j2 = 0; j2 < 4; ++j2)
                    acc[i2][j2] = fmaf(a[i2], bb2[j2], acc[i2][j2]);
        }
        __syncthreads();
    }
    float ls[4], ls2[4];
#pragma unroll
    for (int i2 = 0; i2 < 4; ++i2) { ls[i2] = 0.f; ls2[i2] = 0.f; }
#pragma unroll
    for (int i2 = 0; i2 < 4; ++i2) {
        int co = m0 + tm + i2;
        if (co < Cout) {
            float* op = out + ((size_t)b * Cout + co) * HW + n0 + tn;
#pragma unroll
            for (int j2 = 0; j2 < 4; ++j2) {
                float y = acc[i2][j2];
                op[j2] = y; ls[i2] += y; ls2[i2] += y * y;
            }
        }
    }
    if (statL >= 0) {
#pragma unroll
        for (int i2 = 0; i2 < 4; ++i2) {
            float s = ls[i2], q = ls2[i2];
#pragma unroll
            for (int off = 8; off > 0; off >>= 1) {
                s += __shfl_xor_sync(0xffffffffu, s, off);
                q += __shfl_xor_sync(0xffffffffu, q, off);
            }
            if ((t & 15) == 0) {
                int co = m0 + tm + i2;
                if (co < Cout) {
                    atomicAdd(&g_acc[(statL * 2 + 0) * 192 + co], s);
                    atomicAdd(&g_acc[(statL * 2 + 1) * 192 + co], q);
                }
            }
        }
    }
}

// ---------------- final: pw 180->9 + softmax + disparity expectation -------
__global__ __launch_bounds__(256)
void k_final(const float* __restrict__ in, const float* __restrict__ w,
             const float* __restrict__ gIn, const float* __restrict__ bIn,
             float* __restrict__ out) {
    __shared__ float sW[9 * 180];
    __shared__ float sSc[180], sSh[180];
    int t = threadIdx.x;
    for (int s = t; s < 9 * 180; s += 256) sW[s] = w[s];
    for (int c = t; c < 180; c += 256) {
        float sc, sh;
        bn_from_acc(17, 1.f / NAGG_F, gIn, bIn, c, sc, sh);
        sSc[c] = sc; sSh[c] = sh;
    }
    __syncthreads();
    int pix = blockIdx.x * 256 + t;
    int b = pix / HW, p = pix - b * HW;
    float a[9];
#pragma unroll
    for (int c = 0; c < 9; ++c) a[c] = 0.f;
    for (int ci = 0; ci < 180; ++ci) {
        float v = fmaxf(fmaf(in[((size_t)b * 180 + ci) * HW + p], sSc[ci], sSh[ci]), 0.f);
#pragma unroll
        for (int c = 0; c < 9; ++c) a[c] = fmaf(v, sW[c * 180 + ci], a[c]);
    }
    float m = a[0];
#pragma unroll
    for (int c = 1; c < 9; ++c) m = fmaxf(m, a[c]);
    float den = 0.f, num = 0.f;
#pragma unroll
    for (int c = 0; c < 9; ++c) {
        float e = expf(a[c] - m);
        den += e; num += e * (float)(c - 4);
    }
    out[pix] = num / den;
}

// ------------------------------------------------------------------------
extern "C" void kernel_launch(void* const* d_in, const int* in_sizes, int n_in,
                              void* d_out, int out_size) {
    (void)in_sizes; (void)n_in; (void)out_size;
    const float* x       = (const float*)d_in[0];
    const float* fw0     = (const float*)d_in[1];
    const float* fg0     = (const float*)d_in[2];
    const float* fb0     = (const float*)d_in[3];
    const float* fw      = (const float*)d_in[4];
    const float* fg      = (const float*)d_in[5];
    const float* fb      = (const float*)d_in[6];
    const float* bc_w    = (const float*)d_in[7];
    const float* agg0_dw = (const float*)d_in[8];
    const float* agg0_dg = (const float*)d_in[9];
    const float* agg0_db = (const float*)d_in[10];
    const float* agg0_pw = (const float*)d_in[11];
    const float* agg0_pg = (const float*)d_in[12];
    const float* agg0_pb = (const float*)d_in[13];
    const float* aggm_dw = (const float*)d_in[14];
    const float* aggm_dg = (const float*)d_in[15];
    const float* aggm_db = (const float*)d_in[16];
    const float* aggm_pw = (const float*)d_in[17];
    const float* aggm_pg = (const float*)d_in[18];
    const float* aggm_pb = (const float*)d_in[19];
    const float* last_dw = (const float*)d_in[20];
    const float* last_dg = (const float*)d_in[21];
    const float* last_db = (const float*)d_in[22];
    const float* last_pw = (const float*)d_in[23];
    float* out = (float*)d_out;

    float *fA, *fB, *y0, *y1;
    cudaGetSymbolAddress((void**)&fA, g_fA);
    cudaGetSymbolAddress((void**)&fB, g_fB);
    cudaGetSymbolAddress((void**)&y0, g_y0);
    cudaGetSymbolAddress((void**)&y1, g_y1);

    const int bcSmem = (9072 + 7168) * 4;  // 64960 bytes
    cudaFuncSetAttribute(k_buildcost, cudaFuncAttributeMaxDynamicSharedMemorySize, bcSmem);

    k_zero<<<27, 256>>>();

    // conv0: 1 -> 7, input from x (SAI layout), stats layer 0
    k_conv0<<<dim3(12, 81, 2), dim3(96, 2)>>>(x, fA, fw0);

    const float* cur = fA; float* nxt = fB;
    for (int i = 0; i < 6; ++i) {
        const float* gi = (i == 0) ? fg0 : (fg + (size_t)(i - 1) * 7);
        const float* bi = (i == 0) ? fb0 : (fb + (size_t)(i - 1) * 7);
        k_conv7<<<dim3(12, 81, 2), dim3(96, 2)>>>(cur, nxt, fw + (size_t)i * 441, gi, bi, i, i + 1);
        const float* tmp = cur; cur = nxt; nxt = (float*)tmp;
    }
    // cur holds final pre-activation features; stats in layer 6

    // fused disp_shift + BuildCost -> cv (144 ch) in y0
    k_buildcost<<<dim3(9, 9, 2), 256, bcSmem>>>(cur, y0, bc_w, fg + 35, fb + 35);

    // agg0: dw (no input act) + pw
    k_dw<<<dim3(144, 2), 256>>>(y0, y1, agg0_dw, 144, -1, 0.f, nullptr, nullptr, 7);
    k_pw<<<dim3(144, 3, 2), 256>>>(y1, y0, agg0_pw, 144, 180, 7, agg0_dg, agg0_db, 8);

    // 4 middle blocks
    for (int i = 0; i < 4; ++i) {
        int Ld = 9 + 2 * i, Lp = 10 + 2 * i;
        const float* gp = (i == 0) ? agg0_pg : (aggm_pg + (size_t)(i - 1) * 180);
        const float* bp = (i == 0) ? agg0_pb : (aggm_pb + (size_t)(i - 1) * 180);
        k_dw<<<dim3(180, 2), 256>>>(y0, y1, aggm_dw + (size_t)i * 1620, 180,
                                    Ld - 1, 1.f / NAGG_F, gp, bp, Ld);
        k_pw<<<dim3(144, 3, 2), 256>>>(y1, y0, aggm_pw + (size_t)i * 32400, 180, 180,
                                       Ld, aggm_dg + (size_t)i * 180, aggm_db + (size_t)i * 180, Lp);
    }

    // last dw + final pw/softmax/expectation
    k_dw<<<dim3(180, 2), 256>>>(y0, y1, last_dw, 180, 16, 1.f / NAGG_F,
                                aggm_pg + 3 * 180, aggm_pb + 3 * 180, 17);
    k_final<<<72, 256>>>(y1, last_pw, last_dg, last_db, out);
}

// round 14
// speedup vs baseline: 1.9802x; 1.9802x over previous
#include <cuda_runtime.h>
#include <math.h>

#define ANGR 9
#define NVIEW 81
#define HH 96
#define WW 96
#define HW 9216
#define CF 7
#define BB 2

static const float NINIT_F = 2.0f * 81.0f * 9216.0f;  // 1492992
static const float NAGG_F  = 2.0f * 9216.0f;          // 18432

// ---------------- device scratch (no allocations allowed) ----------------
__device__ float g_fA[BB * CF * NVIEW * HW];   // 41.8 MB
__device__ float g_fB[BB * CF * NVIEW * HW];   // 41.8 MB
__device__ float g_y0[BB * 180 * HW];          // 13.3 MB
__device__ float g_y1[BB * 180 * HW];          // 13.3 MB
__device__ float g_acc[18 * 2 * 192];          // per-layer [sum, sumsq] per channel

// ---------------- zero the stat accumulators ----------------
__global__ void k_zero() {
    int t = blockIdx.x * blockDim.x + threadIdx.x;
    if (t < 18 * 2 * 192) g_acc[t] = 0.f;
}

// ---------------- inline BN finalize from batch stats ----------------
__device__ __forceinline__ void bn_from_acc(int L, float invN,
                                            const float* __restrict__ g,
                                            const float* __restrict__ b,
                                            int c, float& sc, float& sh) {
    float s = g_acc[(L * 2 + 0) * 192 + c];
    float q = g_acc[(L * 2 + 1) * 192 + c];
    float m = s * invN;
    float var = fmaxf(q * invN - m * m, 0.f);
    sc = g[c] * rsqrtf(var + 1e-5f);
    sh = b[c] - m * sc;
}

// ---------------- conv0: 1 -> 7, per-view 3x3, input from x (SAI) ---------
__global__ __launch_bounds__(192)
void k_conv0(const float* __restrict__ in, float* __restrict__ out,
             const float* __restrict__ w) {
    __shared__ float sW[63];
    __shared__ float sPart[6][14];
    int t = threadIdx.y * 96 + threadIdx.x;
    if (t < 63) sW[t] = w[t];
    __syncthreads();

    int b = blockIdx.z, view = blockIdx.y;
    int j = threadIdx.x;
    int i0 = blockIdx.x * 8 + threadIdx.y * 4;

    const float* ibase = in + (size_t)b * 864 * 864
                       + (size_t)(view / ANGR) * 96 * 864 + (size_t)(view % ANGR) * 96;

    float colv[3][6];
#pragma unroll
    for (int rr = 0; rr < 6; ++rr) {
        int i = i0 - 1 + rr;
#pragma unroll
        for (int cc = 0; cc < 3; ++cc) {
            int jj = j - 1 + cc;
            float v = 0.f;
            if (i >= 0 && i < HH && jj >= 0 && jj < WW) v = ibase[i * 864 + jj];
            colv[cc][rr] = v;
        }
    }

    float acc[CF][4];
#pragma unroll
    for (int co = 0; co < CF; ++co)
#pragma unroll
        for (int p = 0; p < 4; ++p) acc[co][p] = 0.f;

#pragma unroll
    for (int ky = 0; ky < 3; ++ky)
#pragma unroll
        for (int kx = 0; kx < 3; ++kx) {
            float wr[CF];
#pragma unroll
            for (int co = 0; co < CF; ++co) wr[co] = sW[co * 9 + ky * 3 + kx];
#pragma unroll
            for (int p = 0; p < 4; ++p) {
                float v = colv[kx][p + ky];
#pragma unroll
                for (int co = 0; co < CF; ++co)
                    acc[co][p] = fmaf(v, wr[co], acc[co][p]);
            }
        }

    float ls[CF], ls2[CF];
#pragma unroll
    for (int co = 0; co < CF; ++co) { ls[co] = 0.f; ls2[co] = 0.f; }
#pragma unroll
    for (int co = 0; co < CF; ++co) {
        float* op = out + ((size_t)(b * CF + co) * NVIEW + view) * HW + j;
#pragma unroll
        for (int p = 0; p < 4; ++p) {
            float y = acc[co][p];
            op[(i0 + p) * WW] = y;
            ls[co] += y; ls2[co] += y * y;
        }
    }
    int lane = t & 31, warp = t >> 5;
#pragma unroll
    for (int co = 0; co < CF; ++co) {
        float s = ls[co], q = ls2[co];
#pragma unroll
        for (int off = 16; off > 0; off >>= 1) {
            s += __shfl_xor_sync(0xffffffffu, s, off);
            q += __shfl_xor_sync(0xffffffffu, q, off);
        }
        if (lane == 0) { sPart[warp][co] = s; sPart[warp][7 + co] = q; }
    }
    __syncthreads();
    if (t < 14) {
        float tot = 0.f;
#pragma unroll
        for (int wp = 0; wp < 6; ++wp) tot += sPart[wp][t];
        atomicAdd(&g_acc[(0 * 2 + (t / 7)) * 192 + (t % 7)], tot);
    }
}

// ---------------- conv7: 7 -> 7 per-view 3x3, smem input tile (R8 exact) ---
// block (96,2): 8 output rows per block; grid (12, 81, 2).
__global__ __launch_bounds__(192)
void k_conv7(const float* __restrict__ in, float* __restrict__ out,
             const float* __restrict__ w,
             const float* __restrict__ gIn, const float* __restrict__ bIn,
             int Lin, int statL) {
    __shared__ float sIn[7][10][100];   // 7000 floats
    __shared__ float sW[441];
    __shared__ float sSc[7], sSh[7];
    __shared__ float sPart[6][14];

    int t = threadIdx.y * 96 + threadIdx.x;
    if (t < 7) {
        float sc, sh;
        bn_from_acc(Lin, 1.f / NINIT_F, gIn, bIn, t, sc, sh);
        sSc[t] = sc; sSh[t] = sh;
    }
    for (int s = t; s < 441; s += 192) sW[s] = w[s];
    __syncthreads();

    int b = blockIdx.z, view = blockIdx.y;
    int i0 = blockIdx.x * 8;
    const float* ib = in + ((size_t)(b * CF) * NVIEW + view) * HW;

    // fill 7 x 10 x 100 zero-padded tile, BN+ReLU at load
    for (int s = t; s < 7000; s += 192) {
        int c = s / 1000;
        int rem = s - c * 1000;
        int r = rem / 100;
        int col = rem - r * 100;
        int ii = i0 - 1 + r, jj = col - 1;
        float v = 0.f;
        if (ii >= 0 && ii < HH && jj >= 0 && jj < WW) {
            v = ib[(size_t)c * NVIEW * HW + ii * WW + jj];
            v = fmaxf(fmaf(v, sSc[c], sSh[c]), 0.f);
        }
        ((float*)sIn)[s] = v;
    }
    __syncthreads();

    int j = threadIdx.x;
    int r0 = threadIdx.y * 4;

    float acc[CF][4];
#pragma unroll
    for (int co = 0; co < CF; ++co)
#pragma unroll
        for (int p = 0; p < 4; ++p) acc[co][p] = 0.f;

    for (int cin = 0; cin < CF; ++cin) {
        float colv[3][6];
#pragma unroll
        for (int rr = 0; rr < 6; ++rr)
#pragma unroll
            for (int cc = 0; cc < 3; ++cc)
                colv[cc][rr] = sIn[cin][r0 + rr][j + cc];
#pragma unroll
        for (int ky = 0; ky < 3; ++ky)
#pragma unroll
            for (int kx = 0; kx < 3; ++kx) {
                float wr[CF];
#pragma unroll
                for (int co = 0; co < CF; ++co)
                    wr[co] = sW[((co * CF + cin) * 3 + ky) * 3 + kx];
#pragma unroll
                for (int p = 0; p < 4; ++p) {
                    float v = colv[kx][p + ky];
#pragma unroll
                    for (int co = 0; co < CF; ++co)
                        acc[co][p] = fmaf(v, wr[co], acc[co][p]);
                }
            }
    }

    int iout = i0 + r0;
    float ls[CF], ls2[CF];
#pragma unroll
    for (int co = 0; co < CF; ++co) { ls[co] = 0.f; ls2[co] = 0.f; }
#pragma unroll
    for (int co = 0; co < CF; ++co) {
        float* op = out + ((size_t)(b * CF + co) * NVIEW + view) * HW + j;
#pragma unroll
        for (int p = 0; p < 4; ++p) {
            float y = acc[co][p];
            op[(iout + p) * WW] = y;
            ls[co] += y; ls2[co] += y * y;
        }
    }

    int lane = t & 31, warp = t >> 5;
#pragma unroll
    for (int co = 0; co < CF; ++co) {
        float s = ls[co], q = ls2[co];
#pragma unroll
        for (int off = 16; off > 0; off >>= 1) {
            s += __shfl_xor_sync(0xffffffffu, s, off);
            q += __shfl_xor_sync(0xffffffffu, q, off);
        }
        if (lane == 0) { sPart[warp][co] = s; sPart[warp][7 + co] = q; }
    }
    __syncthreads();
    if (t < 14) {
        float tot = 0.f;
#pragma unroll
        for (int wp = 0; wp < 6; ++wp) tot += sPart[wp][t];
        atomicAdd(&g_acc[(statL * 2 + (t / 7)) * 192 + (t % 7)], tot);
    }
}

// ---------------- fused disp_shift + BuildCost v2: register gather ---------
// tile 32x16, 2 pixels/thread, weights-only smem, NO syncs in uv mainloop.
// grid (18, 9, 2): 18 tiles (3 x-tiles x 6 y-tiles), 9 groups, 2 batch.
__global__ __launch_bounds__(256)
void k_buildcost(const float* __restrict__ f, float* __restrict__ cv,
                 const float* __restrict__ bcw,
                 const float* __restrict__ g6, const float* __restrict__ b6) {
    __shared__ __align__(16) float sW[81 * 7 * 16];   // 9072 floats = 36.3 KB
    __shared__ float sSc[CF], sSh[CF];

    int t = threadIdx.x;
    int b = blockIdx.z, g = blockIdx.y;
    int d = g - 4;
    int y0 = (blockIdx.x / 3) * 16, x0 = (blockIdx.x % 3) * 32;

    if (t < CF) {
        float sc, sh;
        bn_from_acc(6, 1.f / NINIT_F, g6, b6, t, sc, sh);
        sSc[t] = sc; sSh[t] = sh;
    }
    // weight layout in smem: [uv][c][o]; apply view flip for d>0
    for (int s = t; s < 9072; s += 256) {
        int o = s & 15;
        int c = (s >> 4) % 7;
        int uv = s / 112;
        int u = uv / 9, v = uv % 9;
        int uvs = (d > 0) ? ((8 - u) * 9 + (8 - v)) : uv;
        sW[s] = bcw[((size_t)(16 * g + o) * 7 + c) * 81 + uvs];
    }
    __syncthreads();

    int tx = t & 31, ty = t >> 5;        // pixel (y0+ty, x0+tx) and (y0+ty+8, ...)
    float scr[CF], shr[CF];
#pragma unroll
    for (int c = 0; c < CF; ++c) { scr[c] = sSc[c]; shr[c] = sSh[c]; }

    float acc[2][16];
#pragma unroll
    for (int px = 0; px < 2; ++px)
#pragma unroll
        for (int o = 0; o < 16; ++o) acc[px][o] = 0.f;

    const float* fb = f + (size_t)b * CF * NVIEW * HW;

    int u = 0, v = 0;
    for (int uv = 0; uv < 81; ++uv) {
        int jj  = x0 + tx - d * (v - 4);
        int ii0 = y0 + ty - d * (u - 4);
        bool jok = (jj >= 0) && (jj < WW);

        float fv[2][CF];
#pragma unroll
        for (int px = 0; px < 2; ++px) {
            int ii = ii0 + 8 * px;
            bool ok = jok && (ii >= 0) && (ii < HH);
            const float* base = fb + (size_t)uv * HW + ii * WW + jj;
#pragma unroll
            for (int c = 0; c < CF; ++c) {
                float val = 0.f;
                if (ok)
                    val = fmaxf(fmaf(base[(size_t)c * NVIEW * HW], scr[c], shr[c]), 0.f);
                fv[px][c] = val;
            }
        }

        const float* wuv = sW + uv * 112;
#pragma unroll
        for (int c = 0; c < CF; ++c) {
            const float4* wp = reinterpret_cast<const float4*>(wuv + c * 16);
            float4 w0 = wp[0], w1 = wp[1], w2 = wp[2], w3 = wp[3];
            float wr[16] = {w0.x, w0.y, w0.z, w0.w, w1.x, w1.y, w1.z, w1.w,
                            w2.x, w2.y, w2.z, w2.w, w3.x, w3.y, w3.z, w3.w};
#pragma unroll
            for (int px = 0; px < 2; ++px) {
                float vv = fv[px][c];
#pragma unroll
                for (int o = 0; o < 16; ++o)
                    acc[px][o] = fmaf(vv, wr[o], acc[px][o]);
            }
        }
        if (++v == 9) { v = 0; ++u; }
    }

#pragma unroll
    for (int o = 0; o < 16; ++o) {
        float* op = cv + ((size_t)b * 144 + 16 * g + o) * HW;
#pragma unroll
        for (int px = 0; px < 2; ++px)
            op[(y0 + ty + 8 * px) * WW + (x0 + tx)] = acc[px][o];
    }
}

// ---------------- depthwise 3x3 (pad 1), optional input BN+ReLU ------------
__global__ __launch_bounds__(256)
void k_dw(const float* __restrict__ in, float* __restrict__ out,
          const float* __restrict__ w, int C, int Lin, float invN,
          const float* __restrict__ gIn, const float* __restrict__ bIn,
          int statL) {
    int c = blockIdx.x, b = blockIdx.y, t = threadIdx.x;
    float wr[9];
#pragma unroll
    for (int k = 0; k < 9; ++k) wr[k] = w[c * 9 + k];
    float sc = 1.f, sh = 0.f;
    bool act = (Lin >= 0);
    if (act) bn_from_acc(Lin, invN, gIn, bIn, c, sc, sh);
    const float* ip = in + ((size_t)b * C + c) * HW;
    float* op = out + ((size_t)b * C + c) * HW;
    float ls = 0.f, ls2 = 0.f;
    for (int p = t; p < HW; p += 256) {
        int i = p / 96, j = p - i * 96;
        float sum = 0.f;
#pragma unroll
        for (int dy = -1; dy <= 1; ++dy)
#pragma unroll
            for (int dx = -1; dx <= 1; ++dx) {
                int ii = i + dy, jj = j + dx;
                if (ii >= 0 && ii < HH && jj >= 0 && jj < WW) {
                    float v = ip[ii * WW + jj];
                    if (act) v = fmaxf(fmaf(v, sc, sh), 0.f);
                    sum = fmaf(v, wr[(dy + 1) * 3 + dx + 1], sum);
                }
            }
        op[p] = sum; ls += sum; ls2 += sum * sum;
    }
    __shared__ float sP[8][2];
    int lane = t & 31, wp = t >> 5;
#pragma unroll
    for (int off = 16; off > 0; off >>= 1) {
        ls  += __shfl_xor_sync(0xffffffffu, ls, off);
        ls2 += __shfl_xor_sync(0xffffffffu, ls2, off);
    }
    if (lane == 0) { sP[wp][0] = ls; sP[wp][1] = ls2; }
    __syncthreads();
    if (t == 0) {
        float a = 0.f, q = 0.f;
#pragma unroll
        for (int k = 0; k < 8; ++k) { a += sP[k][0]; q += sP[k][1]; }
        atomicAdd(&g_acc[(statL * 2 + 0) * 192 + c], a);
        atomicAdd(&g_acc[(statL * 2 + 1) * 192 + c], q);
    }
}

// ---------------- pointwise conv = GEMM [Cout x Cin] x [Cin x 9216] --------
// BM=64 (cout) x BN=64 (pix) x BK=16; 256 threads, 4x4 per thread.
__global__ __launch_bounds__(256)
void k_pw(const float* __restrict__ in, float* __restrict__ out,
          const float* __restrict__ w, int Cin, int Cout, int Lin,
          const float* __restrict__ gIn, const float* __restrict__ bIn,
          int statL) {
    __shared__ __align__(16) float sA[16 * 64];
    __shared__ __align__(16) float sB[16 * 64];
    __shared__ float sSc[192], sSh[192];
    int t = threadIdx.x;
    int n0 = blockIdx.x * 64, m0 = blockIdx.y * 64, b = blockIdx.z;
    for (int c = t; c < Cin; c += 256) {
        float sc, sh;
        bn_from_acc(Lin, 1.f / NAGG_F, gIn, bIn, c, sc, sh);
        sSc[c] = sc; sSh[c] = sh;
    }
    int tm = (t >> 4) << 2, tn = (t & 15) << 2;
    float acc[4][4];
#pragma unroll
    for (int i2 = 0; i2 < 4; ++i2)
#pragma unroll
        for (int j2 = 0; j2 < 4; ++j2) acc[i2][j2] = 0.f;
    int Kt = (Cin + 15) >> 4;
    __syncthreads();
    for (int kt = 0; kt < Kt; ++kt) {
        int k0 = kt << 4;
#pragma unroll
        for (int r = 0; r < 4; ++r) {
            int s = t + r * 256;
            int k = s >> 6, mn = s & 63;
            int ci = k0 + k;
            int co = m0 + mn;
            sA[s] = (ci < Cin && co < Cout) ? w[(size_t)co * Cin + ci] : 0.f;
            float xv = 0.f;
            if (ci < Cin)
                xv = fmaxf(fmaf(in[((size_t)b * Cin + ci) * HW + n0 + mn], sSc[ci], sSh[ci]), 0.f);
            sB[s] = xv;
        }
        __syncthreads();
#pragma unroll
        for (int kk = 0; kk < 16; ++kk) {
            float4 av = *reinterpret_cast<const float4*>(&sA[kk * 64 + tm]);
            float4 bv = *reinterpret_cast<const float4*>(&sB[kk * 64 + tn]);
            float a[4] = {av.x, av.y, av.z, av.w};
            float bb2[4] = {bv.x, bv.y, bv.z, bv.w};
#pragma unroll
            for (int i2 = 0; i2 < 4; ++i2)
#pragma unroll
                for (int j2 = 0; j2 < 4; ++j2)
                    acc[i2][j2] = fmaf(a[i2], bb2[j2], acc[i2][j2]);
        }
        __syncthreads();
    }
    float ls[4], ls2[4];
#pragma unroll
    for (int i2 = 0; i2 < 4; ++i2) { ls[i2] = 0.f; ls2[i2] = 0.f; }
#pragma unroll
    for (int i2 = 0; i2 < 4; ++i2) {
        int co = m0 + tm + i2;
        if (co < Cout) {
            float* op = out + ((size_t)b * Cout + co) * HW + n0 + tn;
#pragma unroll
            for (int j2 = 0; j2 < 4; ++j2) {
                float y = acc[i2][j2];
                op[j2] = y; ls[i2] += y; ls2[i2] += y * y;
            }
        }
    }
    if (statL >= 0) {
#pragma unroll
        for (int i2 = 0; i2 < 4; ++i2) {
            float s = ls[i2], q = ls2[i2];
#pragma unroll
            for (int off = 8; off > 0; off >>= 1) {
                s += __shfl_xor_sync(0xffffffffu, s, off);
                q += __shfl_xor_sync(0xffffffffu, q, off);
            }
            if ((t & 15) == 0) {
                int co = m0 + tm + i2;
                if (co < Cout) {
                    atomicAdd(&g_acc[(statL * 2 + 0) * 192 + co], s);
                    atomicAdd(&g_acc[(statL * 2 + 1) * 192 + co], q);
                }
            }
        }
    }
}

// ---------------- final: pw 180->9 + softmax + disparity expectation -------
__global__ __launch_bounds__(256)
void k_final(const float* __restrict__ in, const float* __restrict__ w,
             const float* __restrict__ gIn, const float* __restrict__ bIn,
             float* __restrict__ out) {
    __shared__ float sW[9 * 180];
    __shared__ float sSc[180], sSh[180];
    int t = threadIdx.x;
    for (int s = t; s < 9 * 180; s += 256) sW[s] = w[s];
    for (int c = t; c < 180; c += 256) {
        float sc, sh;
        bn_from_acc(17, 1.f / NAGG_F, gIn, bIn, c, sc, sh);
        sSc[c] = sc; sSh[c] = sh;
    }
    __syncthreads();
    int pix = blockIdx.x * 256 + t;
    int b = pix / HW, p = pix - b * HW;
    float a[9];
#pragma unroll
    for (int c = 0; c < 9; ++c) a[c] = 0.f;
    for (int ci = 0; ci < 180; ++ci) {
        float v = fmaxf(fmaf(in[((size_t)b * 180 + ci) * HW + p], sSc[ci], sSh[ci]), 0.f);
#pragma unroll
        for (int c = 0; c < 9; ++c) a[c] = fmaf(v, sW[c * 180 + ci], a[c]);
    }
    float m = a[0];
#pragma unroll
    for (int c = 1; c < 9; ++c) m = fmaxf(m, a[c]);
    float den = 0.f, num = 0.f;
#pragma unroll
    for (int c = 0; c < 9; ++c) {
        float e = expf(a[c] - m);
        den += e; num += e * (float)(c - 4);
    }
    out[pix] = num / den;
}

// ------------------------------------------------------------------------
extern "C" void kernel_launch(void* const* d_in, const int* in_sizes, int n_in,
                              void* d_out, int out_size) {
    (void)in_sizes; (void)n_in; (void)out_size;
    const float* x       = (const float*)d_in[0];
    const float* fw0     = (const float*)d_in[1];
    const float* fg0     = (const float*)d_in[2];
    const float* fb0     = (const float*)d_in[3];
    const float* fw      = (const float*)d_in[4];
    const float* fg      = (const float*)d_in[5];
    const float* fb      = (const float*)d_in[6];
    const float* bc_w    = (const float*)d_in[7];
    const float* agg0_dw = (const float*)d_in[8];
    const float* agg0_dg = (const float*)d_in[9];
    const float* agg0_db = (const float*)d_in[10];
    const float* agg0_pw = (const float*)d_in[11];
    const float* agg0_pg = (const float*)d_in[12];
    const float* agg0_pb = (const float*)d_in[13];
    const float* aggm_dw = (const float*)d_in[14];
    const float* aggm_dg = (const float*)d_in[15];
    const float* aggm_db = (const float*)d_in[16];
    const float* aggm_pw = (const float*)d_in[17];
    const float* aggm_pg = (const float*)d_in[18];
    const float* aggm_pb = (const float*)d_in[19];
    const float* last_dw = (const float*)d_in[20];
    const float* last_dg = (const float*)d_in[21];
    const float* last_db = (const float*)d_in[22];
    const float* last_pw = (const float*)d_in[23];
    float* out = (float*)d_out;

    float *fA, *fB, *y0, *y1;
    cudaGetSymbolAddress((void**)&fA, g_fA);
    cudaGetSymbolAddress((void**)&fB, g_fB);
    cudaGetSymbolAddress((void**)&y0, g_y0);
    cudaGetSymbolAddress((void**)&y1, g_y1);

    k_zero<<<27, 256>>>();

    // conv0: 1 -> 7, input from x (SAI layout), stats layer 0
    k_conv0<<<dim3(12, 81, 2), dim3(96, 2)>>>(x, fA, fw0);

    const float* cur = fA; float* nxt = fB;
    for (int i = 0; i < 6; ++i) {
        const float* gi = (i == 0) ? fg0 : (fg + (size_t)(i - 1) * 7);
        const float* bi = (i == 0) ? fb0 : (fb + (size_t)(i - 1) * 7);
        k_conv7<<<dim3(12, 81, 2), dim3(96, 2)>>>(cur, nxt, fw + (size_t)i * 441, gi, bi, i, i + 1);
        const float* tmp = cur; cur = nxt; nxt = (float*)tmp;
    }
    // cur holds final pre-activation features; stats in layer 6

    // fused disp_shift + BuildCost -> cv (144 ch) in y0
    k_buildcost<<<dim3(18, 9, 2), 256>>>(cur, y0, bc_w, fg + 35, fb + 35);

    // agg0: dw (no input act) + pw
    k_dw<<<dim3(144, 2), 256>>>(y0, y1, agg0_dw, 144, -1, 0.f, nullptr, nullptr, 7);
    k_pw<<<dim3(144, 3, 2), 256>>>(y1, y0, agg0_pw, 144, 180, 7, agg0_dg, agg0_db, 8);

    // 4 middle blocks
    for (int i = 0; i < 4; ++i) {
        int Ld = 9 + 2 * i, Lp = 10 + 2 * i;
        const float* gp = (i == 0) ? agg0_pg : (aggm_pg + (size_t)(i - 1) * 180);
        const float* bp = (i == 0) ? agg0_pb : (aggm_pb + (size_t)(i - 1) * 180);
        k_dw<<<dim3(180, 2), 256>>>(y0, y1, aggm_dw + (size_t)i * 1620, 180,
                                    Ld - 1, 1.f / NAGG_F, gp, bp, Ld);
        k_pw<<<dim3(144, 3, 2), 256>>>(y1, y0, aggm_pw + (size_t)i * 32400, 180, 180,
                                       Ld, aggm_dg + (size_t)i * 180, aggm_db + (size_t)i * 180, Lp);
    }

    // last dw + final pw/softmax/expectation
    k_dw<<<dim3(180, 2), 256>>>(y0, y1, last_dw, 180, 16, 1.f / NAGG_F,
                                aggm_pg + 3 * 180, aggm_pb + 3 * 180, 17);
    k_final<<<72, 256>>>(y1, last_pw, last_dg, last_db, out);
}

// round 16
// speedup vs baseline: 2.1294x; 1.0754x over previous
#include <cuda_runtime.h>
#include <math.h>

#define ANGR 9
#define NVIEW 81
#define HH 96
#define WW 96
#define HW 9216
#define CF 7
#define BB 2

static const float NINIT_F = 2.0f * 81.0f * 9216.0f;  // 1492992
static const float NAGG_F  = 2.0f * 9216.0f;          // 18432

// ---------------- device scratch (no allocations allowed) ----------------
__device__ float g_fA[BB * CF * NVIEW * HW];   // 41.8 MB
__device__ float g_fB[BB * CF * NVIEW * HW];   // 41.8 MB
__device__ float g_y0[BB * 180 * HW];          // 13.3 MB
__device__ float g_y1[BB * 180 * HW];          // 13.3 MB
__device__ float g_acc[18 * 2 * 192];          // per-layer [sum, sumsq] per channel

// ---------------- zero the stat accumulators ----------------
__global__ void k_zero() {
    int t = blockIdx.x * blockDim.x + threadIdx.x;
    if (t < 18 * 2 * 192) g_acc[t] = 0.f;
}

// ---------------- inline BN finalize from batch stats ----------------
__device__ __forceinline__ void bn_from_acc(int L, float invN,
                                            const float* __restrict__ g,
                                            const float* __restrict__ b,
                                            int c, float& sc, float& sh) {
    float s = g_acc[(L * 2 + 0) * 192 + c];
    float q = g_acc[(L * 2 + 1) * 192 + c];
    float m = s * invN;
    float var = fmaxf(q * invN - m * m, 0.f);
    sc = g[c] * rsqrtf(var + 1e-5f);
    sh = b[c] - m * sc;
}

// ---------------- conv0: 1 -> 7, per-view 3x3, input from x (SAI) ---------
__global__ __launch_bounds__(192)
void k_conv0(const float* __restrict__ in, float* __restrict__ out,
             const float* __restrict__ w) {
    __shared__ float sW[63];
    __shared__ float sPart[6][14];
    int t = threadIdx.y * 96 + threadIdx.x;
    if (t < 63) sW[t] = w[t];
    __syncthreads();

    int b = blockIdx.z, view = blockIdx.y;
    int j = threadIdx.x;
    int i0 = blockIdx.x * 8 + threadIdx.y * 4;

    const float* ibase = in + (size_t)b * 864 * 864
                       + (size_t)(view / ANGR) * 96 * 864 + (size_t)(view % ANGR) * 96;

    float colv[3][6];
#pragma unroll
    for (int rr = 0; rr < 6; ++rr) {
        int i = i0 - 1 + rr;
#pragma unroll
        for (int cc = 0; cc < 3; ++cc) {
            int jj = j - 1 + cc;
            float v = 0.f;
            if (i >= 0 && i < HH && jj >= 0 && jj < WW) v = ibase[i * 864 + jj];
            colv[cc][rr] = v;
        }
    }

    float acc[CF][4];
#pragma unroll
    for (int co = 0; co < CF; ++co)
#pragma unroll
        for (int p = 0; p < 4; ++p) acc[co][p] = 0.f;

#pragma unroll
    for (int ky = 0; ky < 3; ++ky)
#pragma unroll
        for (int kx = 0; kx < 3; ++kx) {
            float wr[CF];
#pragma unroll
            for (int co = 0; co < CF; ++co) wr[co] = sW[co * 9 + ky * 3 + kx];
#pragma unroll
            for (int p = 0; p < 4; ++p) {
                float v = colv[kx][p + ky];
#pragma unroll
                for (int co = 0; co < CF; ++co)
                    acc[co][p] = fmaf(v, wr[co], acc[co][p]);
            }
        }

    float ls[CF], ls2[CF];
#pragma unroll
    for (int co = 0; co < CF; ++co) { ls[co] = 0.f; ls2[co] = 0.f; }
#pragma unroll
    for (int co = 0; co < CF; ++co) {
        float* op = out + ((size_t)(b * CF + co) * NVIEW + view) * HW + j;
#pragma unroll
        for (int p = 0; p < 4; ++p) {
            float y = acc[co][p];
            op[(i0 + p) * WW] = y;
            ls[co] += y; ls2[co] += y * y;
        }
    }
    int lane = t & 31, warp = t >> 5;
#pragma unroll
    for (int co = 0; co < CF; ++co) {
        float s = ls[co], q = ls2[co];
#pragma unroll
        for (int off = 16; off > 0; off >>= 1) {
            s += __shfl_xor_sync(0xffffffffu, s, off);
            q += __shfl_xor_sync(0xffffffffu, q, off);
        }
        if (lane == 0) { sPart[warp][co] = s; sPart[warp][7 + co] = q; }
    }
    __syncthreads();
    if (t < 14) {
        float tot = 0.f;
#pragma unroll
        for (int wp = 0; wp < 6; ++wp) tot += sPart[wp][t];
        atomicAdd(&g_acc[(0 * 2 + (t / 7)) * 192 + (t % 7)], tot);
    }
}

// ---------------- conv7: 7 -> 7 per-view 3x3, smem input tile (R8 exact) ---
// block (96,2): 8 output rows per block; grid (12, 81, 2).
__global__ __launch_bounds__(192)
void k_conv7(const float* __restrict__ in, float* __restrict__ out,
             const float* __restrict__ w,
             const float* __restrict__ gIn, const float* __restrict__ bIn,
             int Lin, int statL) {
    __shared__ float sIn[7][10][100];   // 7000 floats
    __shared__ float sW[441];
    __shared__ float sSc[7], sSh[7];
    __shared__ float sPart[6][14];

    int t = threadIdx.y * 96 + threadIdx.x;
    if (t < 7) {
        float sc, sh;
        bn_from_acc(Lin, 1.f / NINIT_F, gIn, bIn, t, sc, sh);
        sSc[t] = sc; sSh[t] = sh;
    }
    for (int s = t; s < 441; s += 192) sW[s] = w[s];
    __syncthreads();

    int b = blockIdx.z, view = blockIdx.y;
    int i0 = blockIdx.x * 8;
    const float* ib = in + ((size_t)(b * CF) * NVIEW + view) * HW;

    // fill 7 x 10 x 100 zero-padded tile, BN+ReLU at load
    for (int s = t; s < 7000; s += 192) {
        int c = s / 1000;
        int rem = s - c * 1000;
        int r = rem / 100;
        int col = rem - r * 100;
        int ii = i0 - 1 + r, jj = col - 1;
        float v = 0.f;
        if (ii >= 0 && ii < HH && jj >= 0 && jj < WW) {
            v = ib[(size_t)c * NVIEW * HW + ii * WW + jj];
            v = fmaxf(fmaf(v, sSc[c], sSh[c]), 0.f);
        }
        ((float*)sIn)[s] = v;
    }
    __syncthreads();

    int j = threadIdx.x;
    int r0 = threadIdx.y * 4;

    float acc[CF][4];
#pragma unroll
    for (int co = 0; co < CF; ++co)
#pragma unroll
        for (int p = 0; p < 4; ++p) acc[co][p] = 0.f;

    for (int cin = 0; cin < CF; ++cin) {
        float colv[3][6];
#pragma unroll
        for (int rr = 0; rr < 6; ++rr)
#pragma unroll
            for (int cc = 0; cc < 3; ++cc)
                colv[cc][rr] = sIn[cin][r0 + rr][j + cc];
#pragma unroll
        for (int ky = 0; ky < 3; ++ky)
#pragma unroll
            for (int kx = 0; kx < 3; ++kx) {
                float wr[CF];
#pragma unroll
                for (int co = 0; co < CF; ++co)
                    wr[co] = sW[((co * CF + cin) * 3 + ky) * 3 + kx];
#pragma unroll
                for (int p = 0; p < 4; ++p) {
                    float v = colv[kx][p + ky];
#pragma unroll
                    for (int co = 0; co < CF; ++co)
                        acc[co][p] = fmaf(v, wr[co], acc[co][p]);
                }
            }
    }

    int iout = i0 + r0;
    float ls[CF], ls2[CF];
#pragma unroll
    for (int co = 0; co < CF; ++co) { ls[co] = 0.f; ls2[co] = 0.f; }
#pragma unroll
    for (int co = 0; co < CF; ++co) {
        float* op = out + ((size_t)(b * CF + co) * NVIEW + view) * HW + j;
#pragma unroll
        for (int p = 0; p < 4; ++p) {
            float y = acc[co][p];
            op[(iout + p) * WW] = y;
            ls[co] += y; ls2[co] += y * y;
        }
    }

    int lane = t & 31, warp = t >> 5;
#pragma unroll
    for (int co = 0; co < CF; ++co) {
        float s = ls[co], q = ls2[co];
#pragma unroll
        for (int off = 16; off > 0; off >>= 1) {
            s += __shfl_xor_sync(0xffffffffu, s, off);
            q += __shfl_xor_sync(0xffffffffu, q, off);
        }
        if (lane == 0) { sPart[warp][co] = s; sPart[warp][7 + co] = q; }
    }
    __syncthreads();
    if (t < 14) {
        float tot = 0.f;
#pragma unroll
        for (int wp = 0; wp < 6; ++wp) tot += sPart[wp][t];
        atomicAdd(&g_acc[(statL * 2 + (t / 7)) * 192 + (t % 7)], tot);
    }
}

// ---------------- fused disp_shift + BuildCost v2: register gather ---------
// tile 32x16, 2 pixels/thread, weights-only smem, NO syncs in uv mainloop.
// grid (18, 9, 2): 18 tiles (3 x-tiles x 6 y-tiles), 9 groups, 2 batch.
__global__ __launch_bounds__(256)
void k_buildcost(const float* __restrict__ f, float* __restrict__ cv,
                 const float* __restrict__ bcw,
                 const float* __restrict__ g6, const float* __restrict__ b6) {
    __shared__ __align__(16) float sW[81 * 7 * 16];   // 9072 floats = 36.3 KB
    __shared__ float sSc[CF], sSh[CF];

    int t = threadIdx.x;
    int b = blockIdx.z, g = blockIdx.y;
    int d = g - 4;
    int y0 = (blockIdx.x / 3) * 16, x0 = (blockIdx.x % 3) * 32;

    if (t < CF) {
        float sc, sh;
        bn_from_acc(6, 1.f / NINIT_F, g6, b6, t, sc, sh);
        sSc[t] = sc; sSh[t] = sh;
    }
    // weight layout in smem: [uv][c][o]; apply view flip for d>0
    for (int s = t; s < 9072; s += 256) {
        int o = s & 15;
        int c = (s >> 4) % 7;
        int uv = s / 112;
        int u = uv / 9, v = uv % 9;
        int uvs = (d > 0) ? ((8 - u) * 9 + (8 - v)) : uv;
        sW[s] = bcw[((size_t)(16 * g + o) * 7 + c) * 81 + uvs];
    }
    __syncthreads();

    int tx = t & 31, ty = t >> 5;        // pixel (y0+ty, x0+tx) and (y0+ty+8, ...)
    float scr[CF], shr[CF];
#pragma unroll
    for (int c = 0; c < CF; ++c) { scr[c] = sSc[c]; shr[c] = sSh[c]; }

    float acc[2][16];
#pragma unroll
    for (int px = 0; px < 2; ++px)
#pragma unroll
        for (int o = 0; o < 16; ++o) acc[px][o] = 0.f;

    const float* fb = f + (size_t)b * CF * NVIEW * HW;

    int u = 0, v = 0;
    for (int uv = 0; uv < 81; ++uv) {
        int jj  = x0 + tx - d * (v - 4);
        int ii0 = y0 + ty - d * (u - 4);
        bool jok = (jj >= 0) && (jj < WW);

        float fv[2][CF];
#pragma unroll
        for (int px = 0; px < 2; ++px) {
            int ii = ii0 + 8 * px;
            bool ok = jok && (ii >= 0) && (ii < HH);
            const float* base = fb + (size_t)uv * HW + ii * WW + jj;
#pragma unroll
            for (int c = 0; c < CF; ++c) {
                float val = 0.f;
                if (ok)
                    val = fmaxf(fmaf(base[(size_t)c * NVIEW * HW], scr[c], shr[c]), 0.f);
                fv[px][c] = val;
            }
        }

        const float* wuv = sW + uv * 112;
#pragma unroll
        for (int c = 0; c < CF; ++c) {
            const float4* wp = reinterpret_cast<const float4*>(wuv + c * 16);
            float4 w0 = wp[0], w1 = wp[1], w2 = wp[2], w3 = wp[3];
            float wr[16] = {w0.x, w0.y, w0.z, w0.w, w1.x, w1.y, w1.z, w1.w,
                            w2.x, w2.y, w2.z, w2.w, w3.x, w3.y, w3.z, w3.w};
#pragma unroll
            for (int px = 0; px < 2; ++px) {
                float vv = fv[px][c];
#pragma unroll
                for (int o = 0; o < 16; ++o)
                    acc[px][o] = fmaf(vv, wr[o], acc[px][o]);
            }
        }
        if (++v == 9) { v = 0; ++u; }
    }

#pragma unroll
    for (int o = 0; o < 16; ++o) {
        float* op = cv + ((size_t)b * 144 + 16 * g + o) * HW;
#pragma unroll
        for (int px = 0; px < 2; ++px)
            op[(y0 + ty + 8 * px) * WW + (x0 + tx)] = acc[px][o];
    }
}

// ---------------- depthwise 3x3 (pad 1), rolling 3-row register window -----
// block (96,4): tx = column, ty = 24-row strip. grid (C, 2).
__global__ __launch_bounds__(384)
void k_dw(const float* __restrict__ in, float* __restrict__ out,
          const float* __restrict__ w, int C, int Lin, float invN,
          const float* __restrict__ gIn, const float* __restrict__ bIn,
          int statL) {
    int c = blockIdx.x, b = blockIdx.y;
    int j = threadIdx.x, ty = threadIdx.y;
    int t = ty * 96 + j;
    float wr[9];
#pragma unroll
    for (int k = 0; k < 9; ++k) wr[k] = w[c * 9 + k];
    float sc = 1.f, sh = 0.f;
    bool act = (Lin >= 0);
    if (act) bn_from_acc(Lin, invN, gIn, bIn, c, sc, sh);
    const float* ip = in + ((size_t)b * C + c) * HW;
    float* op = out + ((size_t)b * C + c) * HW;

    bool jl = (j > 0), jr = (j < 95);
    int rbase = ty * 24;

    float a0, a1, a2, b0, b1, b2;
    {
        int r = rbase - 1;
        if (r >= 0) {
            const float* rp = ip + r * WW;
            float vm = rp[j];
            float vl = jl ? rp[j - 1] : 0.f;
            float vrt = jr ? rp[j + 1] : 0.f;
            if (act) {
                vm  = fmaxf(fmaf(vm,  sc, sh), 0.f);
                vl  = jl ? fmaxf(fmaf(vl,  sc, sh), 0.f) : 0.f;
                vrt = jr ? fmaxf(fmaf(vrt, sc, sh), 0.f) : 0.f;
            }
            a0 = vl; a1 = vm; a2 = vrt;
        } else { a0 = a1 = a2 = 0.f; }
        const float* rp = ip + rbase * WW;
        float vm = rp[j];
        float vl = jl ? rp[j - 1] : 0.f;
        float vrt = jr ? rp[j + 1] : 0.f;
        if (act) {
            vm  = fmaxf(fmaf(vm,  sc, sh), 0.f);
            vl  = jl ? fmaxf(fmaf(vl,  sc, sh), 0.f) : 0.f;
            vrt = jr ? fmaxf(fmaf(vrt, sc, sh), 0.f) : 0.f;
        }
        b0 = vl; b1 = vm; b2 = vrt;
    }

    float ls = 0.f, ls2 = 0.f;
    for (int rr = 0; rr < 24; ++rr) {
        int r = rbase + rr;
        float c0, c1, c2;
        int rn = r + 1;
        if (rn < HH) {
            const float* rp = ip + rn * WW;
            float vm = rp[j];
            float vl = jl ? rp[j - 1] : 0.f;
            float vrt = jr ? rp[j + 1] : 0.f;
            if (act) {
                vm  = fmaxf(fmaf(vm,  sc, sh), 0.f);
                vl  = jl ? fmaxf(fmaf(vl,  sc, sh), 0.f) : 0.f;
                vrt = jr ? fmaxf(fmaf(vrt, sc, sh), 0.f) : 0.f;
            }
            c0 = vl; c1 = vm; c2 = vrt;
        } else { c0 = c1 = c2 = 0.f; }
        float sum = a0 * wr[0];
        sum = fmaf(a1, wr[1], sum); sum = fmaf(a2, wr[2], sum);
        sum = fmaf(b0, wr[3], sum); sum = fmaf(b1, wr[4], sum);
        sum = fmaf(b2, wr[5], sum); sum = fmaf(c0, wr[6], sum);
        sum = fmaf(c1, wr[7], sum); sum = fmaf(c2, wr[8], sum);
        op[r * WW + j] = sum;
        ls += sum; ls2 += sum * sum;
        a0 = b0; a1 = b1; a2 = b2;
        b0 = c0; b1 = c1; b2 = c2;
    }

    __shared__ float sP[12][2];
    int lane = t & 31, wp = t >> 5;
#pragma unroll
    for (int off = 16; off > 0; off >>= 1) {
        ls  += __shfl_xor_sync(0xffffffffu, ls, off);
        ls2 += __shfl_xor_sync(0xffffffffu, ls2, off);
    }
    if (lane == 0) { sP[wp][0] = ls; sP[wp][1] = ls2; }
    __syncthreads();
    if (t == 0) {
        float a = 0.f, q = 0.f;
#pragma unroll
        for (int k = 0; k < 12; ++k) { a += sP[k][0]; q += sP[k][1]; }
        atomicAdd(&g_acc[(statL * 2 + 0) * 192 + c], a);
        atomicAdd(&g_acc[(statL * 2 + 1) * 192 + c], q);
    }
}

// ---------------- pointwise conv = GEMM [Cout x Cin] x [Cin x 9216] --------
// BM=64 (cout) x BN=64 (pix) x BK=16; 256 threads, 4x4 per thread.
__global__ __launch_bounds__(256)
void k_pw(const float* __restrict__ in, float* __restrict__ out,
          const float* __restrict__ w, int Cin, int Cout, int Lin,
          const float* __restrict__ gIn, const float* __restrict__ bIn,
          int statL) {
    __shared__ __align__(16) float sA[16 * 64];
    __shared__ __align__(16) float sB[16 * 64];
    __shared__ float sSc[192], sSh[192];
    int t = threadIdx.x;
    int n0 = blockIdx.x * 64, m0 = blockIdx.y * 64, b = blockIdx.z;
    for (int c = t; c < Cin; c += 256) {
        float sc, sh;
        bn_from_acc(Lin, 1.f / NAGG_F, gIn, bIn, c, sc, sh);
        sSc[c] = sc; sSh[c] = sh;
    }
    int tm = (t >> 4) << 2, tn = (t & 15) << 2;
    float acc[4][4];
#pragma unroll
    for (int i2 = 0; i2 < 4; ++i2)
#pragma unroll
        for (int j2 = 0; j2 < 4; ++j2) acc[i2][j2] = 0.f;
    int Kt = (Cin + 15) >> 4;
    __syncthreads();
    for (int kt = 0; kt < Kt; ++kt) {
        int k0 = kt << 4;
#pragma unroll
        for (int r = 0; r < 4; ++r) {
            int s = t + r * 256;
            int k = s >> 6, mn = s & 63;
            int ci = k0 + k;
            int co = m0 + mn;
            sA[s] = (ci < Cin && co < Cout) ? w[(size_t)co * Cin + ci] : 0.f;
            float xv = 0.f;
            if (ci < Cin)
                xv = fmaxf(fmaf(in[((size_t)b * Cin + ci) * HW + n0 + mn], sSc[ci], sSh[ci]), 0.f);
            sB[s] = xv;
        }
        __syncthreads();
#pragma unroll
        for (int kk = 0; kk < 16; ++kk) {
            float4 av = *reinterpret_cast<const float4*>(&sA[kk * 64 + tm]);
            float4 bv = *reinterpret_cast<const float4*>(&sB[kk * 64 + tn]);
            float a[4] = {av.x, av.y, av.z, av.w};
            float bb2[4] = {bv.x, bv.y, bv.z, bv.w};
#pragma unroll
            for (int i2 = 0; i2 < 4; ++i2)
#pragma unroll
                for (int j2 = 0; j2 < 4; ++j2)
                    acc[i2][j2] = fmaf(a[i2], bb2[j2], acc[i2][j2]);
        }
        __syncthreads();
    }
    float ls[4], ls2[4];
#pragma unroll
    for (int i2 = 0; i2 < 4; ++i2) { ls[i2] = 0.f; ls2[i2] = 0.f; }
#pragma unroll
    for (int i2 = 0; i2 < 4; ++i2) {
        int co = m0 + tm + i2;
        if (co < Cout) {
            float* op = out + ((size_t)b * Cout + co) * HW + n0 + tn;
#pragma unroll
            for (int j2 = 0; j2 < 4; ++j2) {
                float y = acc[i2][j2];
                op[j2] = y; ls[i2] += y; ls2[i2] += y * y;
            }
        }
    }
    if (statL >= 0) {
#pragma unroll
        for (int i2 = 0; i2 < 4; ++i2) {
            float s = ls[i2], q = ls2[i2];
#pragma unroll
            for (int off = 8; off > 0; off >>= 1) {
                s += __shfl_xor_sync(0xffffffffu, s, off);
                q += __shfl_xor_sync(0xffffffffu, q, off);
            }
            if ((t & 15) == 0) {
                int co = m0 + tm + i2;
                if (co < Cout) {
                    atomicAdd(&g_acc[(statL * 2 + 0) * 192 + co], s);
                    atomicAdd(&g_acc[(statL * 2 + 1) * 192 + co], q);
                }
            }
        }
    }
}

// ---------------- final: pw 180->9 + softmax + disparity expectation -------
__global__ __launch_bounds__(256)
void k_final(const float* __restrict__ in, const float* __restrict__ w,
             const float* __restrict__ gIn, const float* __restrict__ bIn,
             float* __restrict__ out) {
    __shared__ float sW[9 * 180];
    __shared__ float sSc[180], sSh[180];
    int t = threadIdx.x;
    for (int s = t; s < 9 * 180; s += 256) sW[s] = w[s];
    for (int c = t; c < 180; c += 256) {
        float sc, sh;
        bn_from_acc(17, 1.f / NAGG_F, gIn, bIn, c, sc, sh);
        sSc[c] = sc; sSh[c] = sh;
    }
    __syncthreads();
    int pix = blockIdx.x * 256 + t;
    int b = pix / HW, p = pix - b * HW;
    float a[9];
#pragma unroll
    for (int c = 0; c < 9; ++c) a[c] = 0.f;
    for (int ci = 0; ci < 180; ++ci) {
        float v = fmaxf(fmaf(in[((size_t)b * 180 + ci) * HW + p], sSc[ci], sSh[ci]), 0.f);
#pragma unroll
        for (int c = 0; c < 9; ++c) a[c] = fmaf(v, sW[c * 180 + ci], a[c]);
    }
    float m = a[0];
#pragma unroll
    for (int c = 1; c < 9; ++c) m = fmaxf(m, a[c]);
    float den = 0.f, num = 0.f;
#pragma unroll
    for (int c = 0; c < 9; ++c) {
        float e = expf(a[c] - m);
        den += e; num += e * (float)(c - 4);
    }
    out[pix] = num / den;
}

// ------------------------------------------------------------------------
extern "C" void kernel_launch(void* const* d_in, const int* in_sizes, int n_in,
                              void* d_out, int out_size) {
    (void)in_sizes; (void)n_in; (void)out_size;
    const float* x       = (const float*)d_in[0];
    const float* fw0     = (const float*)d_in[1];
    const float* fg0     = (const float*)d_in[2];
    const float* fb0     = (const float*)d_in[3];
    const float* fw      = (const float*)d_in[4];
    const float* fg      = (const float*)d_in[5];
    const float* fb      = (const float*)d_in[6];
    const float* bc_w    = (const float*)d_in[7];
    const float* agg0_dw = (const float*)d_in[8];
    const float* agg0_dg = (const float*)d_in[9];
    const float* agg0_db = (const float*)d_in[10];
    const float* agg0_pw = (const float*)d_in[11];
    const float* agg0_pg = (const float*)d_in[12];
    const float* agg0_pb = (const float*)d_in[13];
    const float* aggm_dw = (const float*)d_in[14];
    const float* aggm_dg = (const float*)d_in[15];
    const float* aggm_db = (const float*)d_in[16];
    const float* aggm_pw = (const float*)d_in[17];
    const float* aggm_pg = (const float*)d_in[18];
    const float* aggm_pb = (const float*)d_in[19];
    const float* last_dw = (const float*)d_in[20];
    const float* last_dg = (const float*)d_in[21];
    const float* last_db = (const float*)d_in[22];
    const float* last_pw = (const float*)d_in[23];
    float* out = (float*)d_out;

    float *fA, *fB, *y0, *y1;
    cudaGetSymbolAddress((void**)&fA, g_fA);
    cudaGetSymbolAddress((void**)&fB, g_fB);
    cudaGetSymbolAddress((void**)&y0, g_y0);
    cudaGetSymbolAddress((void**)&y1, g_y1);

    k_zero<<<27, 256>>>();

    // conv0: 1 -> 7, input from x (SAI layout), stats layer 0
    k_conv0<<<dim3(12, 81, 2), dim3(96, 2)>>>(x, fA, fw0);

    const float* cur = fA; float* nxt = fB;
    for (int i = 0; i < 6; ++i) {
        const float* gi = (i == 0) ? fg0 : (fg + (size_t)(i - 1) * 7);
        const float* bi = (i == 0) ? fb0 : (fb + (size_t)(i - 1) * 7);
        k_conv7<<<dim3(12, 81, 2), dim3(96, 2)>>>(cur, nxt, fw + (size_t)i * 441, gi, bi, i, i + 1);
        const float* tmp = cur; cur = nxt; nxt = (float*)tmp;
    }
    // cur holds final pre-activation features; stats in layer 6

    // fused disp_shift + BuildCost -> cv (144 ch) in y0
    k_buildcost<<<dim3(18, 9, 2), 256>>>(cur, y0, bc_w, fg + 35, fb + 35);

    // agg0: dw (no input act) + pw
    k_dw<<<dim3(144, 2), dim3(96, 4)>>>(y0, y1, agg0_dw, 144, -1, 0.f, nullptr, nullptr, 7);
    k_pw<<<dim3(144, 3, 2), 256>>>(y1, y0, agg0_pw, 144, 180, 7, agg0_dg, agg0_db, 8);

    // 4 middle blocks
    for (int i = 0; i < 4; ++i) {
        int Ld = 9 + 2 * i, Lp = 10 + 2 * i;
        const float* gp = (i == 0) ? agg0_pg : (aggm_pg + (size_t)(i - 1) * 180);
        const float* bp = (i == 0) ? agg0_pb : (aggm_pb + (size_t)(i - 1) * 180);
        k_dw<<<dim3(180, 2), dim3(96, 4)>>>(y0, y1, aggm_dw + (size_t)i * 1620, 180,
                                            Ld - 1, 1.f / NAGG_F, gp, bp, Ld);
        k_pw<<<dim3(144, 3, 2), 256>>>(y1, y0, aggm_pw + (size_t)i * 32400, 180, 180,
                                       Ld, aggm_dg + (size_t)i * 180, aggm_db + (size_t)i * 180, Lp);
    }

    // last dw + final pw/softmax/expectation
    k_dw<<<dim3(180, 2), dim3(96, 4)>>>(y0, y1, last_dw, 180, 16, 1.f / NAGG_F,
                                        aggm_pg + 3 * 180, aggm_pb + 3 * 180, 17);
    k_final<<<72, 256>>>(y1, last_pw, last_dg, last_db, out);
}